// round 3
// baseline (speedup 1.0000x reference)
#include <cuda_runtime.h>
#include <math.h>

#define E_N 300000
#define V_N 20000
#define G_N 32
#define D_F 128
#define H_F 256

// ---------------- scratch (static device globals; no runtime allocation) ----------------
__device__ float g_e_pre[E_N * D_F];
__device__ float g_v_pre[V_N * D_F];
__device__ float g_u_pre[G_N * D_F];
__device__ float g_Va[V_N * H_F];
__device__ float g_Vb[V_N * H_F];
__device__ float g_U0[G_N * H_F];
__device__ float g_UN0[G_N * H_F];
__device__ float g_eh1[E_N * H_F];
__device__ float g_eh2[E_N * H_F];
__device__ float g_ve_sum[V_N * D_F];
__device__ int   g_ve_cnt[V_N];
__device__ float g_ue_sum[G_N * D_F];
__device__ int   g_ue_cnt[G_N];
__device__ float g_uv_sum[G_N * D_F];
__device__ int   g_uv_cnt[G_N];
__device__ int   g_gsrc[E_N];
__device__ float g_ncat[V_N * 2 * D_F];
__device__ float g_nh1[V_N * H_F];
__device__ float g_nh2[V_N * H_F];
__device__ float g_ucat[G_N * 3 * D_F];
__device__ float g_ah1[G_N * H_F];
__device__ float g_ah2[G_N * H_F];

// ---------------- helpers ----------------
__device__ __forceinline__ float softplusf(float x) {
    // logaddexp(x, 0) = max(x,0) + log1p(exp(-|x|))
    return fmaxf(x, 0.f) + __logf(1.f + __expf(-fabsf(x)));
}

typedef unsigned long long ull;
__device__ __forceinline__ ull pk2(float a, float b) {
    ull r; asm("mov.b64 %0, {%1, %2};" : "=l"(r) : "f"(a), "f"(b)); return r;
}
__device__ __forceinline__ ull dup2(float a) {
    ull r; asm("mov.b64 %0, {%1, %1};" : "=l"(r) : "f"(a)); return r;
}
__device__ __forceinline__ void up2(ull v, float& a, float& b) {
    asm("mov.b64 {%0, %1}, %2;" : "=f"(a), "=f"(b) : "l"(v));
}
__device__ __forceinline__ ull fma2(ull a, ull b, ull c) {
    ull d; asm("fma.rn.f32x2 %0, %1, %2, %3;" : "=l"(d) : "l"(a), "l"(b), "l"(c)); return d;
}

// ---------------- fused GEMM: out = act(A@B + bias + E0[idx0] + E1[idx1] + E2[idx2]) ----------------
// optional: atomic scatter-add of (pre-skip, post-act) value into at0/at1; skip added after act.
// Tiles: BM=64, BN=128, BK=16, 128 threads, 8x8 per-thread register tile, fp32x2 FMA.
__global__ __launch_bounds__(128) void gemm_fused(
    const float* __restrict__ A, int lda,
    const float* __restrict__ B, int ldb,
    const float* __restrict__ bias,
    const float* __restrict__ E0, const int* __restrict__ E0i,
    const float* __restrict__ E1, const int* __restrict__ E1i,
    const float* __restrict__ E2, const int* __restrict__ E2i,
    const float* __restrict__ skip,
    float* __restrict__ at0, const int* __restrict__ at0i,
    float* __restrict__ at1, const int* __restrict__ at1i,
    float* __restrict__ out,
    int M, int N, int K, int act)
{
    __shared__ float As[16][64];
    __shared__ float Bs[16][128];
    const int tid  = threadIdx.x;
    const int row0 = blockIdx.y * 64;
    const int col0 = blockIdx.x * 128;
    const int tr = tid >> 4, tc = tid & 15;

    ull acc[8][4];
#pragma unroll
    for (int i = 0; i < 8; i++)
#pragma unroll
        for (int j = 0; j < 4; j++) acc[i][j] = 0ull;

    for (int kt = 0; kt < K; kt += 16) {
#pragma unroll
        for (int i = 0; i < 2; i++) {
            int f  = tid + i * 128;          // 0..255 float4 slots
            int ar = f >> 2, ak = (f & 3) << 2;
            float4 v = make_float4(0.f, 0.f, 0.f, 0.f);
            if (row0 + ar < M)
                v = *(const float4*)(A + (size_t)(row0 + ar) * lda + kt + ak);
            As[ak    ][ar] = v.x;
            As[ak + 1][ar] = v.y;
            As[ak + 2][ar] = v.z;
            As[ak + 3][ar] = v.w;
        }
#pragma unroll
        for (int i = 0; i < 4; i++) {
            int f  = tid + i * 128;          // 0..511 float4 slots
            int br = f >> 5, bc = (f & 31) << 2;
            *(float4*)&Bs[br][bc] = *(const float4*)(B + (size_t)(kt + br) * ldb + col0 + bc);
        }
        __syncthreads();
#pragma unroll
        for (int kk = 0; kk < 16; kk++) {
            float4 a0 = *(const float4*)&As[kk][tr * 8];
            float4 a1 = *(const float4*)&As[kk][tr * 8 + 4];
            float4 b0 = *(const float4*)&Bs[kk][tc * 8];
            float4 b1 = *(const float4*)&Bs[kk][tc * 8 + 4];
            ull bp[4] = { pk2(b0.x, b0.y), pk2(b0.z, b0.w), pk2(b1.x, b1.y), pk2(b1.z, b1.w) };
            float av[8] = { a0.x, a0.y, a0.z, a0.w, a1.x, a1.y, a1.z, a1.w };
#pragma unroll
            for (int i = 0; i < 8; i++) {
                ull ap = dup2(av[i]);
#pragma unroll
                for (int j = 0; j < 4; j++) acc[i][j] = fma2(ap, bp[j], acc[i][j]);
            }
        }
        __syncthreads();
    }

    const int rbase = row0 + tr * 8;
    const int cbase = col0 + tc * 8;
#pragma unroll
    for (int i = 0; i < 8; i++) {
        int grow = rbase + i;
        if (grow >= M) break;
        float vals[8];
#pragma unroll
        for (int j = 0; j < 4; j++) up2(acc[i][j], vals[2 * j], vals[2 * j + 1]);
        const float* p0 = E0 ? E0 + (size_t)E0i[grow] * N : (const float*)0;
        const float* p1 = E1 ? E1 + (size_t)E1i[grow] * N : (const float*)0;
        const float* p2 = E2 ? E2 + (size_t)E2i[grow] * N : (const float*)0;
        float* q0 = at0 ? at0 + (size_t)at0i[grow] * N : (float*)0;
        float* q1 = at1 ? at1 + (size_t)at1i[grow] * N : (float*)0;
#pragma unroll
        for (int j = 0; j < 8; j++) {
            int gcol = cbase + j;
            float v = vals[j];
            if (bias) v += bias[gcol];
            if (p0)   v += p0[gcol];
            if (p1)   v += p1[gcol];
            if (p2)   v += p2[gcol];
            if (act)  v = softplusf(v);
            if (q0) atomicAdd(q0 + gcol, v);
            if (q1) atomicAdd(q1 + gcol, v);
            if (skip) v += skip[(size_t)grow * N + gcol];
            out[(size_t)grow * N + gcol] = v;
        }
    }
}

// ---------------- small GEMM (tiny M, e.g. graph-level, 32 rows): one thread per output ----------------
__global__ void small_gemm(const float* __restrict__ A, int lda,
                           const float* __restrict__ B, int ldb,
                           const float* __restrict__ bias,
                           const float* __restrict__ skip,
                           float* __restrict__ out,
                           int M, int N, int K, int act)
{
    int idx = blockIdx.x * blockDim.x + threadIdx.x;
    if (idx >= M * N) return;
    int row = idx / N, col = idx % N;
    float s = bias ? bias[col] : 0.f;
    const float* a = A + (size_t)row * lda;
    for (int k = 0; k < K; k++) s += a[k] * B[(size_t)k * ldb + col];
    if (act)  s = softplusf(s);
    if (skip) s += skip[(size_t)row * N + col];
    out[(size_t)row * N + col] = s;
}

// ---------------- misc kernels ----------------
__global__ void zero_kernel() {
    int i = blockIdx.x * blockDim.x + threadIdx.x;
    if (i < V_N * D_F) g_ve_sum[i] = 0.f;
    if (i < G_N * D_F) { g_ue_sum[i] = 0.f; g_uv_sum[i] = 0.f; }
    if (i < V_N) g_ve_cnt[i] = 0;
    if (i < G_N) { g_ue_cnt[i] = 0; g_uv_cnt[i] = 0; }
}

__global__ void count_edges(const int* __restrict__ src, const int* __restrict__ dst,
                            const int* __restrict__ n2g) {
    int i = blockIdx.x * blockDim.x + threadIdx.x;
    if (i >= E_N) return;
    int g = n2g[src[i]];
    g_gsrc[i] = g;
    atomicAdd(&g_ve_cnt[dst[i]], 1);
    atomicAdd(&g_ue_cnt[g], 1);
}

__global__ void count_nodes(const int* __restrict__ n2g) {
    int i = blockIdx.x * blockDim.x + threadIdx.x;
    if (i >= V_N) return;
    atomicAdd(&g_uv_cnt[n2g[i]], 1);
}

__global__ void build_ncat() {
    int i = blockIdx.x * blockDim.x + threadIdx.x;
    if (i >= V_N * 2 * D_F) return;
    int row = i >> 8, c = i & 255;
    float v;
    if (c < D_F) v = g_v_pre[row * D_F + c];
    else         v = g_ve_sum[row * D_F + (c - D_F)] / fmaxf((float)g_ve_cnt[row], 1.f);
    g_ncat[i] = v;
}

__global__ void build_ucat() {
    int i = blockIdx.x * blockDim.x + threadIdx.x;
    if (i >= G_N * 3 * D_F) return;
    int row = i / (3 * D_F), c = i % (3 * D_F);
    float v;
    if (c < D_F)          v = g_u_pre[row * D_F + c];
    else if (c < 2 * D_F) v = g_ue_sum[row * D_F + (c - D_F)]     / fmaxf((float)g_ue_cnt[row], 1.f);
    else                  v = g_uv_sum[row * D_F + (c - 2 * D_F)] / fmaxf((float)g_uv_cnt[row], 1.f);
    g_ucat[i] = v;
}

// ---------------- launch ----------------
extern "C" void kernel_launch(void* const* d_in, const int* in_sizes, int n_in,
                              void* d_out, int out_size) {
    (void)in_sizes; (void)n_in; (void)out_size;
    const float* edge_feat  = (const float*)d_in[0];
    const float* node_feat  = (const float*)d_in[1];
    const float* graph_attr = (const float*)d_in[2];
    const int*   src = (const int*)d_in[3];
    const int*   dst = (const int*)d_in[4];
    const int*   n2g = (const int*)d_in[5];
    const float* peW = (const float*)d_in[6],  *peb = (const float*)d_in[7];
    const float* pnW = (const float*)d_in[8],  *pnb = (const float*)d_in[9];
    const float* paW = (const float*)d_in[10], *pab = (const float*)d_in[11];
    const float* eW0 = (const float*)d_in[12], *eb0 = (const float*)d_in[13];
    const float* eW1 = (const float*)d_in[14], *eb1 = (const float*)d_in[15];
    const float* eW2 = (const float*)d_in[16], *eb2 = (const float*)d_in[17];
    const float* nW0 = (const float*)d_in[18], *nb0 = (const float*)d_in[19];
    const float* nW1 = (const float*)d_in[20], *nb1 = (const float*)d_in[21];
    const float* nW2 = (const float*)d_in[22], *nb2 = (const float*)d_in[23];
    const float* aW0 = (const float*)d_in[24], *ab0 = (const float*)d_in[25];
    const float* aW1 = (const float*)d_in[26], *ab1 = (const float*)d_in[27];
    const float* aW2 = (const float*)d_in[28], *ab2 = (const float*)d_in[29];

    float* out_e = (float*)d_out;
    float* out_v = out_e + (size_t)E_N * D_F;
    float* out_u = out_v + (size_t)V_N * D_F;

    float *e_pre, *v_pre, *u_pre, *Va, *Vb, *U0, *UN0, *eh1, *eh2;
    float *ve_sum, *ue_sum, *uv_sum, *ncat, *nh1, *nh2, *ucat, *ah1, *ah2;
    int *gsrc;
#define SYMF(p, s) { void* _t; cudaGetSymbolAddress(&_t, s); p = (float*)_t; }
#define SYMI(p, s) { void* _t; cudaGetSymbolAddress(&_t, s); p = (int*)_t; }
    SYMF(e_pre, g_e_pre)  SYMF(v_pre, g_v_pre)  SYMF(u_pre, g_u_pre)
    SYMF(Va, g_Va)        SYMF(Vb, g_Vb)        SYMF(U0, g_U0)   SYMF(UN0, g_UN0)
    SYMF(eh1, g_eh1)      SYMF(eh2, g_eh2)
    SYMF(ve_sum, g_ve_sum) SYMF(ue_sum, g_ue_sum) SYMF(uv_sum, g_uv_sum)
    SYMF(ncat, g_ncat)    SYMF(nh1, g_nh1)      SYMF(nh2, g_nh2)
    SYMF(ucat, g_ucat)    SYMF(ah1, g_ah1)      SYMF(ah2, g_ah2)
    SYMI(gsrc, g_gsrc)
#undef SYMF
#undef SYMI

    const int T = 128;
    dim3 gE1(1, (E_N + 63) / 64), gE2(2, (E_N + 63) / 64);
    dim3 gV1(1, (V_N + 63) / 64), gV2(2, (V_N + 63) / 64);

    zero_kernel<<<(V_N * D_F + 255) / 256, 256>>>();
    count_edges<<<(E_N + 255) / 256, 256>>>(src, dst, n2g);
    count_nodes<<<(V_N + 255) / 256, 256>>>(n2g);

    // pre-dense (softplus)
    gemm_fused<<<gE1, T>>>(edge_feat, D_F, peW, D_F, peb,
                           0, 0, 0, 0, 0, 0, 0, 0, 0, 0, 0,
                           e_pre, E_N, D_F, D_F, 1);
    gemm_fused<<<gV1, T>>>(node_feat, D_F, pnW, D_F, pnb,
                           0, 0, 0, 0, 0, 0, 0, 0, 0, 0, 0,
                           v_pre, V_N, D_F, D_F, 1);
    small_gemm<<<(G_N * D_F + 255) / 256, 256>>>(graph_attr, D_F, paW, D_F, pab, 0,
                                                 u_pre, G_N, D_F, D_F, 1);

    // factored first edge layer: precompute per-node / per-graph partial products
    gemm_fused<<<gV2, T>>>(v_pre, D_F, eW0, H_F, 0,
                           0, 0, 0, 0, 0, 0, 0, 0, 0, 0, 0,
                           Va, V_N, H_F, D_F, 0);
    gemm_fused<<<gV2, T>>>(v_pre, D_F, eW0 + 128 * H_F, H_F, 0,
                           0, 0, 0, 0, 0, 0, 0, 0, 0, 0, 0,
                           Vb, V_N, H_F, D_F, 0);
    small_gemm<<<(G_N * H_F + 255) / 256, 256>>>(u_pre, D_F, eW0 + 384 * H_F, H_F, 0, 0,
                                                 U0, G_N, H_F, D_F, 0);
    small_gemm<<<(G_N * H_F + 255) / 256, 256>>>(u_pre, D_F, nW0 + 256 * H_F, H_F, 0, 0,
                                                 UN0, G_N, H_F, D_F, 0);

    // edge MLP
    gemm_fused<<<gE2, T>>>(e_pre, D_F, eW0 + 256 * H_F, H_F, eb0,
                           Va, src, Vb, dst, U0, gsrc, 0, 0, 0, 0, 0,
                           eh1, E_N, H_F, D_F, 1);
    gemm_fused<<<gE2, T>>>(eh1, H_F, eW1, H_F, eb1,
                           0, 0, 0, 0, 0, 0, 0, 0, 0, 0, 0,
                           eh2, E_N, H_F, H_F, 1);
    gemm_fused<<<gE1, T>>>(eh2, H_F, eW2, D_F, eb2,
                           0, 0, 0, 0, 0, 0, edge_feat,
                           ve_sum, dst, ue_sum, gsrc,
                           out_e, E_N, D_F, H_F, 1);

    // node MLP
    build_ncat<<<(V_N * 2 * D_F + 255) / 256, 256>>>();
    gemm_fused<<<gV2, T>>>(ncat, 2 * D_F, nW0, H_F, nb0,
                           UN0, n2g, 0, 0, 0, 0, 0, 0, 0, 0, 0,
                           nh1, V_N, H_F, 2 * D_F, 1);
    gemm_fused<<<gV2, T>>>(nh1, H_F, nW1, H_F, nb1,
                           0, 0, 0, 0, 0, 0, 0, 0, 0, 0, 0,
                           nh2, V_N, H_F, H_F, 1);
    gemm_fused<<<gV1, T>>>(nh2, H_F, nW2, D_F, nb2,
                           0, 0, 0, 0, 0, 0, node_feat,
                           uv_sum, n2g, 0, 0,
                           out_v, V_N, D_F, H_F, 1);

    // graph-attr MLP
    build_ucat<<<(G_N * 3 * D_F + 255) / 256, 256>>>();
    small_gemm<<<(G_N * H_F + 255) / 256, 256>>>(ucat, 3 * D_F, aW0, H_F, ab0, 0,
                                                 ah1, G_N, H_F, 3 * D_F, 1);
    small_gemm<<<(G_N * H_F + 255) / 256, 256>>>(ah1, H_F, aW1, H_F, ab1, 0,
                                                 ah2, G_N, H_F, H_F, 1);
    small_gemm<<<(G_N * D_F + 255) / 256, 256>>>(ah2, H_F, aW2, D_F, ab2, graph_attr,
                                                 out_u, G_N, D_F, H_F, 1);
}

// round 7
// speedup vs baseline: 1.5404x; 1.5404x over previous
#include <cuda_runtime.h>
#include <cuda_bf16.h>
#include <math.h>
#include <stdint.h>

#define E_N 300000
#define V_N 20000
#define G_N 32
#define D_F 128
#define H_F 256

// ---------------- scratch (static device globals) ----------------
__device__ float g_e_pre[E_N * D_F];
__device__ float g_v_pre[V_N * D_F];
__device__ float g_u_pre[G_N * D_F];
__device__ float g_Va[V_N * H_F];
__device__ float g_Vb[V_N * H_F];
__device__ float g_U0[G_N * H_F];
__device__ float g_UN0[G_N * H_F];
__device__ float g_eh1[E_N * H_F];
__device__ float g_eh2[E_N * H_F];
__device__ float g_ve_sum[V_N * D_F];
__device__ int   g_ve_cnt[V_N];
__device__ float g_ue_sum[G_N * D_F];
__device__ int   g_ue_cnt[G_N];
__device__ float g_uv_sum[G_N * D_F];
__device__ int   g_uv_cnt[G_N];
__device__ int   g_gsrc[E_N];
__device__ float g_ncat[V_N * 2 * D_F];
__device__ float g_nh1[V_N * H_F];
__device__ float g_nh2[V_N * H_F];
__device__ float g_ucat[G_N * 3 * D_F];
__device__ float g_ah1[G_N * H_F];
__device__ float g_ah2[G_N * H_F];

// pre-split weights (bf16 hi/lo), layout [N][K] row-major
#define WT_TOTAL 393216
__device__ __nv_bfloat16 g_wthi[WT_TOTAL];
__device__ __nv_bfloat16 g_wtlo[WT_TOTAL];
// offsets (elements)
#define OFF_PE  0
#define OFF_PN  16384
#define OFF_WVA 32768
#define OFF_WVB 65536
#define OFF_WE1 98304
#define OFF_EW1 131072
#define OFF_EW2 196608
#define OFF_NW0 229376
#define OFF_NW1 294912
#define OFF_NW2 360448

typedef unsigned long long ull;

// ---------------- helpers ----------------
__device__ __forceinline__ float softplusf(float x) {
    return fmaxf(x, 0.f) + __logf(1.f + __expf(-fabsf(x)));
}

__device__ __forceinline__ uint32_t smem_to_u32(const void* p) {
    uint32_t a;
    asm("{ .reg .u64 t; cvta.to.shared.u64 t, %1; cvt.u32.u64 %0, t; }" : "=r"(a) : "l"(p));
    return a;
}

__device__ __forceinline__ void mma16816(float* d, const uint32_t* a, const uint32_t* b) {
    asm volatile(
        "mma.sync.aligned.m16n8k16.row.col.f32.bf16.bf16.f32 "
        "{%0,%1,%2,%3}, {%4,%5,%6,%7}, {%8,%9}, {%0,%1,%2,%3};"
        : "+f"(d[0]), "+f"(d[1]), "+f"(d[2]), "+f"(d[3])
        : "r"(a[0]), "r"(a[1]), "r"(a[2]), "r"(a[3]), "r"(b[0]), "r"(b[1]));
}

#define CP_ASYNC16(dst_u32, src_ptr) \
    asm volatile("cp.async.cg.shared.global [%0], [%1], 16;" :: "r"(dst_u32), "l"(src_ptr))
#define CP_COMMIT() asm volatile("cp.async.commit_group;" ::: "memory")

// ---------------- weight prep: fp32 [K][N] -> bf16 hi/lo [N][K] ----------------
__global__ void prep_weight(const float* __restrict__ W, int K, int N,
                            __nv_bfloat16* __restrict__ hi, __nv_bfloat16* __restrict__ lo)
{
    int idx = blockIdx.x * blockDim.x + threadIdx.x;
    if (idx >= K * N) return;
    int k = idx / N, n = idx % N;
    float x = W[idx];
    __nv_bfloat16 h = __float2bfloat16_rn(x);
    __nv_bfloat16 l = __float2bfloat16_rn(x - __bfloat162float(h));
    size_t pos = (size_t)n * K + k;
    hi[pos] = h;
    lo[pos] = l;
}

// ---------------- mma.sync GEMM ----------------
// out = act(A@W^T + bias + E0[i0] + E1[i1] + E2[i2]) (+atomic scatter, +skip)
// A fp32 [M][K]; W pre-split bf16 [Ntot][K]. Block tile 128x128, BK=32 (bf16),
// 256 threads = 8 warps (4 m x 2 n), warp tile 32x64. 3-way bf16 split.
#define AS 40   // smem row stride in halves (80B, odd*4 banks -> conflict-free)
#define STG_H 20480  // halves per stage (4 * 128*40)

__global__ __launch_bounds__(256, 1)
void mma_gemm(const float* __restrict__ A, int K, int Ntot,
              const __nv_bfloat16* __restrict__ Whi, const __nv_bfloat16* __restrict__ Wlo,
              const float* __restrict__ bias,
              const float* __restrict__ E0, const int* __restrict__ E0i,
              const float* __restrict__ E1, const int* __restrict__ E1i,
              const float* __restrict__ E2, const int* __restrict__ E2i,
              const float* __restrict__ skip,
              float* __restrict__ at0, const int* __restrict__ at0i,
              float* __restrict__ at1, const int* __restrict__ at1i,
              float* __restrict__ out, int M, int act)
{
    extern __shared__ __align__(16) __nv_bfloat16 sm[];
    const uint32_t sbase = smem_to_u32(sm);
    const int tid  = threadIdx.x;
    const int lane = tid & 31, wid = tid >> 5;
    const int wm = wid & 3, wn = wid >> 2;
    const int colblk = blockIdx.x << 7;
    const int row0   = blockIdx.y << 7;

    const int nch = K >> 5;

    // A loader mapping: row = tid>>1 (0..127), half = tid&1 (16 floats each)
    const int lar = tid >> 1, lah = tid & 1;
    const bool larv = (row0 + lar) < M;
    const float* aRow = A + (size_t)(row0 + lar) * K + lah * 16;

    float acc[2][8][4];
#pragma unroll
    for (int mt = 0; mt < 2; mt++)
#pragma unroll
        for (int nt = 0; nt < 8; nt++)
#pragma unroll
            for (int c = 0; c < 4; c++) acc[mt][nt][c] = 0.f;

    float4 ar[4];

#define LDG_A(c) do { \
    if (larv) { \
        const float4* _p = (const float4*)(aRow + (c) * 32); \
        ar[0] = _p[0]; ar[1] = _p[1]; ar[2] = _p[2]; ar[3] = _p[3]; \
    } else { \
        ar[0] = ar[1] = ar[2] = ar[3] = make_float4(0.f, 0.f, 0.f, 0.f); \
    } } while (0)

#define STS_A(st) do { \
    const int _base = (st) * STG_H + lar * AS + lah * 16; \
    _Pragma("unroll") \
    for (int q = 0; q < 4; q++) { \
        __nv_bfloat162 h0 = __floats2bfloat162_rn(ar[q].x, ar[q].y); \
        __nv_bfloat162 h1 = __floats2bfloat162_rn(ar[q].z, ar[q].w); \
        float2 f0 = __bfloat1622float2(h0); \
        float2 f1 = __bfloat1622float2(h1); \
        __nv_bfloat162 l0 = __floats2bfloat162_rn(ar[q].x - f0.x, ar[q].y - f0.y); \
        __nv_bfloat162 l1 = __floats2bfloat162_rn(ar[q].z - f1.x, ar[q].w - f1.y); \
        ull hp = (ull)(*(uint32_t*)&h0) | ((ull)(*(uint32_t*)&h1) << 32); \
        ull lp = (ull)(*(uint32_t*)&l0) | ((ull)(*(uint32_t*)&l1) << 32); \
        *(ull*)&sm[_base + q * 4]        = hp; \
        *(ull*)&sm[_base + 5120 + q * 4] = lp; \
    } } while (0)

#define CPA_B(c, st) do { \
    const int _boff = (st) * STG_H + 10240; \
    _Pragma("unroll") \
    for (int i = 0; i < 2; i++) { \
        int _idx = tid + i * 256; \
        int _r = _idx >> 2, _s = _idx & 3; \
        const __nv_bfloat16* _sh = Whi + (size_t)(colblk + _r) * K + (c) * 32 + _s * 8; \
        const __nv_bfloat16* _sl = Wlo + (size_t)(colblk + _r) * K + (c) * 32 + _s * 8; \
        uint32_t _dh = sbase + (uint32_t)(_boff + _r * AS + _s * 8) * 2; \
        uint32_t _dl = _dh + 5120 * 2; \
        CP_ASYNC16(_dh, _sh); \
        CP_ASYNC16(_dl, _sl); \
    } } while (0)

    // prologue
    LDG_A(0);
    CPA_B(0, 0);
    CP_COMMIT();
    STS_A(0);

    const int arow = wm * 32 + (lane >> 2);
    const int acol = (lane & 3) * 2;

    for (int c = 0; c < nch; c++) {
        const int nxt = c + 1;
        if (nxt < nch) {
            LDG_A(nxt);
            CPA_B(nxt, nxt & 1);
            CP_COMMIT();
            asm volatile("cp.async.wait_group 1;" ::: "memory");
        } else {
            asm volatile("cp.async.wait_group 0;" ::: "memory");
        }
        __syncthreads();

        // compute stage c&1
        {
            const int S = (c & 1) * STG_H;
            const __nv_bfloat16* Ah = sm + S;
            const __nv_bfloat16* Al = Ah + 5120;
            const __nv_bfloat16* Bh = Ah + 10240;
            const __nv_bfloat16* Bl = Ah + 15360;
#pragma unroll
            for (int ks = 0; ks < 2; ks++) {
                uint32_t ah[2][4], al[2][4];
#pragma unroll
                for (int mt = 0; mt < 2; mt++)
#pragma unroll
                    for (int r = 0; r < 4; r++) {
                        int idx = (arow + mt * 16 + (r & 1) * 8) * AS
                                + acol + (r >> 1) * 8 + ks * 16;
                        ah[mt][r] = *(const uint32_t*)&Ah[idx];
                        al[mt][r] = *(const uint32_t*)&Al[idx];
                    }
                uint32_t bh[8][2], bl[8][2];
#pragma unroll
                for (int nt = 0; nt < 8; nt++)
#pragma unroll
                    for (int r = 0; r < 2; r++) {
                        int idx = (wn * 64 + nt * 8 + (lane >> 2)) * AS
                                + acol + r * 8 + ks * 16;
                        bh[nt][r] = *(const uint32_t*)&Bh[idx];
                        bl[nt][r] = *(const uint32_t*)&Bl[idx];
                    }
#pragma unroll
                for (int mt = 0; mt < 2; mt++)
#pragma unroll
                    for (int nt = 0; nt < 8; nt++) {
                        mma16816(acc[mt][nt], ah[mt], bh[nt]);
                        mma16816(acc[mt][nt], ah[mt], bl[nt]);
                        mma16816(acc[mt][nt], al[mt], bh[nt]);
                    }
            }
        }
        if (nxt < nch) STS_A(nxt & 1);
        __syncthreads();
    }

    // ---- epilogue ----
#pragma unroll
    for (int mt = 0; mt < 2; mt++) {
#pragma unroll
        for (int h = 0; h < 2; h++) {
            const int grow = row0 + wm * 32 + mt * 16 + (lane >> 2) + h * 8;
            if (grow >= M) continue;
            const float* p0 = E0 ? E0 + (size_t)E0i[grow] * Ntot : (const float*)0;
            const float* p1 = E1 ? E1 + (size_t)E1i[grow] * Ntot : (const float*)0;
            const float* p2 = E2 ? E2 + (size_t)E2i[grow] * Ntot : (const float*)0;
            float* q0 = at0 ? at0 + (size_t)at0i[grow] * Ntot : (float*)0;
            float* q1 = at1 ? at1 + (size_t)at1i[grow] * Ntot : (float*)0;
            const float* sk = skip ? skip + (size_t)grow * Ntot : (const float*)0;
            float* op = out + (size_t)grow * Ntot;
#pragma unroll
            for (int nt = 0; nt < 8; nt++) {
                const int col = colblk + wn * 64 + nt * 8 + (lane & 3) * 2;
                float v0 = acc[mt][nt][h * 2 + 0];
                float v1 = acc[mt][nt][h * 2 + 1];
                if (bias) { v0 += bias[col]; v1 += bias[col + 1]; }
                if (p0)   { v0 += p0[col];  v1 += p0[col + 1]; }
                if (p1)   { v0 += p1[col];  v1 += p1[col + 1]; }
                if (p2)   { v0 += p2[col];  v1 += p2[col + 1]; }
                if (act)  { v0 = softplusf(v0); v1 = softplusf(v1); }
                if (q0)   { atomicAdd(q0 + col, v0); atomicAdd(q0 + col + 1, v1); }
                if (q1)   { atomicAdd(q1 + col, v0); atomicAdd(q1 + col + 1, v1); }
                if (sk)   { v0 += sk[col]; v1 += sk[col + 1]; }
                float2 o; o.x = v0; o.y = v1;
                *(float2*)(op + col) = o;
            }
        }
    }
}

// ---------------- small GEMM (graph-level, 32 rows) ----------------
__global__ void small_gemm(const float* __restrict__ A, int lda,
                           const float* __restrict__ B, int ldb,
                           const float* __restrict__ bias,
                           const float* __restrict__ skip,
                           float* __restrict__ out,
                           int M, int N, int K, int act)
{
    int idx = blockIdx.x * blockDim.x + threadIdx.x;
    if (idx >= M * N) return;
    int row = idx / N, col = idx % N;
    float s = bias ? bias[col] : 0.f;
    const float* a = A + (size_t)row * lda;
    for (int k = 0; k < K; k++) s += a[k] * B[(size_t)k * ldb + col];
    if (act)  s = softplusf(s);
    if (skip) s += skip[(size_t)row * N + col];
    out[(size_t)row * N + col] = s;
}

// ---------------- misc kernels ----------------
__global__ void zero_kernel() {
    int i = blockIdx.x * blockDim.x + threadIdx.x;
    if (i < V_N * D_F) g_ve_sum[i] = 0.f;
    if (i < G_N * D_F) { g_ue_sum[i] = 0.f; g_uv_sum[i] = 0.f; }
    if (i < V_N) g_ve_cnt[i] = 0;
    if (i < G_N) { g_ue_cnt[i] = 0; g_uv_cnt[i] = 0; }
}

__global__ void count_edges(const int* __restrict__ src, const int* __restrict__ dst,
                            const int* __restrict__ n2g) {
    int i = blockIdx.x * blockDim.x + threadIdx.x;
    if (i >= E_N) return;
    int g = n2g[src[i]];
    g_gsrc[i] = g;
    atomicAdd(&g_ve_cnt[dst[i]], 1);
    atomicAdd(&g_ue_cnt[g], 1);
}

__global__ void count_nodes(const int* __restrict__ n2g) {
    int i = blockIdx.x * blockDim.x + threadIdx.x;
    if (i >= V_N) return;
    atomicAdd(&g_uv_cnt[n2g[i]], 1);
}

__global__ void build_ncat() {
    int i = blockIdx.x * blockDim.x + threadIdx.x;
    if (i >= V_N * 2 * D_F) return;
    int row = i >> 8, c = i & 255;
    float v;
    if (c < D_F) v = g_v_pre[row * D_F + c];
    else         v = g_ve_sum[row * D_F + (c - D_F)] / fmaxf((float)g_ve_cnt[row], 1.f);
    g_ncat[i] = v;
}

__global__ void build_ucat() {
    int i = blockIdx.x * blockDim.x + threadIdx.x;
    if (i >= G_N * 3 * D_F) return;
    int row = i / (3 * D_F), c = i % (3 * D_F);
    float v;
    if (c < D_F)          v = g_u_pre[row * D_F + c];
    else if (c < 2 * D_F) v = g_ue_sum[row * D_F + (c - D_F)]     / fmaxf((float)g_ue_cnt[row], 1.f);
    else                  v = g_uv_sum[row * D_F + (c - 2 * D_F)] / fmaxf((float)g_uv_cnt[row], 1.f);
    g_ucat[i] = v;
}

// ---------------- launch ----------------
extern "C" void kernel_launch(void* const* d_in, const int* in_sizes, int n_in,
                              void* d_out, int out_size) {
    (void)in_sizes; (void)n_in; (void)out_size;
    const float* edge_feat  = (const float*)d_in[0];
    const float* node_feat  = (const float*)d_in[1];
    const float* graph_attr = (const float*)d_in[2];
    const int*   src = (const int*)d_in[3];
    const int*   dst = (const int*)d_in[4];
    const int*   n2g = (const int*)d_in[5];
    const float* peW = (const float*)d_in[6],  *peb = (const float*)d_in[7];
    const float* pnW = (const float*)d_in[8],  *pnb = (const float*)d_in[9];
    const float* paW = (const float*)d_in[10], *pab = (const float*)d_in[11];
    const float* eW0 = (const float*)d_in[12], *eb0 = (const float*)d_in[13];
    const float* eW1 = (const float*)d_in[14], *eb1 = (const float*)d_in[15];
    const float* eW2 = (const float*)d_in[16], *eb2 = (const float*)d_in[17];
    const float* nW0 = (const float*)d_in[18], *nb0 = (const float*)d_in[19];
    const float* nW1 = (const float*)d_in[20], *nb1 = (const float*)d_in[21];
    const float* nW2 = (const float*)d_in[22], *nb2 = (const float*)d_in[23];
    const float* aW0 = (const float*)d_in[24], *ab0 = (const float*)d_in[25];
    const float* aW1 = (const float*)d_in[26], *ab1 = (const float*)d_in[27];
    const float* aW2 = (const float*)d_in[28], *ab2 = (const float*)d_in[29];

    float* out_e = (float*)d_out;
    float* out_v = out_e + (size_t)E_N * D_F;
    float* out_u = out_v + (size_t)V_N * D_F;

    float *e_pre, *v_pre, *u_pre, *Va, *Vb, *U0, *UN0, *eh1, *eh2;
    float *ve_sum, *ue_sum, *uv_sum, *ncat, *nh1, *nh2, *ucat, *ah1, *ah2;
    int *gsrc;
    __nv_bfloat16 *wthi, *wtlo;
#define SYMX(p, s, T) { void* _t; cudaGetSymbolAddress(&_t, s); p = (T*)_t; }
    SYMX(e_pre, g_e_pre, float)   SYMX(v_pre, g_v_pre, float)   SYMX(u_pre, g_u_pre, float)
    SYMX(Va, g_Va, float)         SYMX(Vb, g_Vb, float)
    SYMX(U0, g_U0, float)         SYMX(UN0, g_UN0, float)
    SYMX(eh1, g_eh1, float)       SYMX(eh2, g_eh2, float)
    SYMX(ve_sum, g_ve_sum, float) SYMX(ue_sum, g_ue_sum, float) SYMX(uv_sum, g_uv_sum, float)
    SYMX(ncat, g_ncat, float)     SYMX(nh1, g_nh1, float)       SYMX(nh2, g_nh2, float)
    SYMX(ucat, g_ucat, float)     SYMX(ah1, g_ah1, float)       SYMX(ah2, g_ah2, float)
    SYMX(gsrc, g_gsrc, int)
    SYMX(wthi, g_wthi, __nv_bfloat16)  SYMX(wtlo, g_wtlo, __nv_bfloat16)
#undef SYMX

    const int SMEM = 2 * STG_H * 2;  // 81920 bytes
    cudaFuncSetAttribute(mma_gemm, cudaFuncAttributeMaxDynamicSharedMemorySize, SMEM);

    const int TE = (E_N + 127) / 128;   // 2344
    const int TV = (V_N + 127) / 128;   // 157
    const float* Z = 0; const int* ZI = 0; float* ZF = 0;

    zero_kernel<<<(V_N * D_F + 255) / 256, 256>>>();
    count_edges<<<(E_N + 255) / 256, 256>>>(src, dst, n2g);
    count_nodes<<<(V_N + 255) / 256, 256>>>(n2g);

    // weight prep (split + transpose to [N][K])
#define PREP(W, K, N, OFF) prep_weight<<<((K)*(N) + 255) / 256, 256>>>(W, K, N, wthi + (OFF), wtlo + (OFF))
    PREP(peW,            128, 128, OFF_PE);
    PREP(pnW,            128, 128, OFF_PN);
    PREP(eW0,            128, 256, OFF_WVA);
    PREP(eW0 + 128*256,  128, 256, OFF_WVB);
    PREP(eW0 + 256*256,  128, 256, OFF_WE1);
    PREP(eW1,            256, 256, OFF_EW1);
    PREP(eW2,            256, 128, OFF_EW2);
    PREP(nW0,            256, 256, OFF_NW0);
    PREP(nW1,            256, 256, OFF_NW1);
    PREP(nW2,            256, 128, OFF_NW2);
#undef PREP

#define GEMM(NT, NB, ...) mma_gemm<<<dim3((NT)/128, (NB)), 256, SMEM>>>(__VA_ARGS__)

    // pre-dense
    GEMM(128, TE, edge_feat, 128, 128, wthi + OFF_PE, wtlo + OFF_PE, peb,
         Z, ZI, Z, ZI, Z, ZI, Z, ZF, ZI, ZF, ZI, e_pre, E_N, 1);
    GEMM(128, TV, node_feat, 128, 128, wthi + OFF_PN, wtlo + OFF_PN, pnb,
         Z, ZI, Z, ZI, Z, ZI, Z, ZF, ZI, ZF, ZI, v_pre, V_N, 1);
    small_gemm<<<(G_N * D_F + 255) / 256, 256>>>(graph_attr, D_F, paW, D_F, pab, 0,
                                                 u_pre, G_N, D_F, D_F, 1);

    // factored first edge layer partials
    GEMM(256, TV, v_pre, 128, 256, wthi + OFF_WVA, wtlo + OFF_WVA, Z,
         Z, ZI, Z, ZI, Z, ZI, Z, ZF, ZI, ZF, ZI, Va, V_N, 0);
    GEMM(256, TV, v_pre, 128, 256, wthi + OFF_WVB, wtlo + OFF_WVB, Z,
         Z, ZI, Z, ZI, Z, ZI, Z, ZF, ZI, ZF, ZI, Vb, V_N, 0);
    small_gemm<<<(G_N * H_F + 255) / 256, 256>>>(u_pre, D_F, eW0 + 384 * H_F, H_F, 0, 0,
                                                 U0, G_N, H_F, D_F, 0);
    small_gemm<<<(G_N * H_F + 255) / 256, 256>>>(u_pre, D_F, nW0 + 256 * H_F, H_F, 0, 0,
                                                 UN0, G_N, H_F, D_F, 0);

    // edge MLP
    GEMM(256, TE, e_pre, 128, 256, wthi + OFF_WE1, wtlo + OFF_WE1, eb0,
         Va, src, Vb, dst, U0, gsrc, Z, ZF, ZI, ZF, ZI, eh1, E_N, 1);
    GEMM(256, TE, eh1, 256, 256, wthi + OFF_EW1, wtlo + OFF_EW1, eb1,
         Z, ZI, Z, ZI, Z, ZI, Z, ZF, ZI, ZF, ZI, eh2, E_N, 1);
    GEMM(128, TE, eh2, 256, 128, wthi + OFF_EW2, wtlo + OFF_EW2, eb2,
         Z, ZI, Z, ZI, Z, ZI, edge_feat,
         ve_sum, dst, ue_sum, gsrc, out_e, E_N, 1);

    // node MLP
    build_ncat<<<(V_N * 2 * D_F + 255) / 256, 256>>>();
    GEMM(256, TV, ncat, 256, 256, wthi + OFF_NW0, wtlo + OFF_NW0, nb0,
         UN0, n2g, Z, ZI, Z, ZI, Z, ZF, ZI, ZF, ZI, nh1, V_N, 1);
    GEMM(256, TV, nh1, 256, 256, wthi + OFF_NW1, wtlo + OFF_NW1, nb1,
         Z, ZI, Z, ZI, Z, ZI, Z, ZF, ZI, ZF, ZI, nh2, V_N, 1);
    GEMM(128, TV, nh2, 256, 128, wthi + OFF_NW2, wtlo + OFF_NW2, nb2,
         Z, ZI, Z, ZI, Z, ZI, node_feat,
         uv_sum, n2g, ZF, ZI, out_v, V_N, 1);

    // graph-attr MLP
    build_ucat<<<(G_N * 3 * D_F + 255) / 256, 256>>>();
    small_gemm<<<(G_N * H_F + 255) / 256, 256>>>(ucat, 3 * D_F, aW0, H_F, ab0, 0,
                                                 ah1, G_N, H_F, 3 * D_F, 1);
    small_gemm<<<(G_N * H_F + 255) / 256, 256>>>(ah1, H_F, aW1, H_F, ab1, 0,
                                                 ah2, G_N, H_F, H_F, 1);
    small_gemm<<<(G_N * D_F + 255) / 256, 256>>>(ah2, H_F, aW2, D_F, ab2, graph_attr,
                                                 out_u, G_N, D_F, H_F, 1);
}

// round 9
// speedup vs baseline: 1.9615x; 1.2734x over previous
#include <cuda_runtime.h>
#include <cuda_bf16.h>
#include <math.h>
#include <stdint.h>

#define E_N 300000
#define V_N 20000
#define G_N 32
#define D_F 128
#define H_F 256

// ---------------- scratch (static device globals) ----------------
__device__ float g_e_pre[E_N * D_F];
__device__ float g_v_pre[V_N * D_F];
__device__ float g_u_pre[G_N * D_F];
__device__ float g_Va[V_N * H_F];
__device__ float g_Vb[V_N * H_F];
__device__ float g_U0[G_N * H_F];
__device__ float g_UN0[G_N * H_F];
__device__ float g_eh1[E_N * H_F];
__device__ float g_eh2[E_N * H_F];
__device__ float g_ve_sum[V_N * D_F];
__device__ int   g_ve_cnt[V_N];
__device__ float g_ue_sum[G_N * D_F];
__device__ int   g_ue_cnt[G_N];
__device__ float g_uv_sum[G_N * D_F];
__device__ int   g_uv_cnt[G_N];
__device__ int   g_gsrc[E_N];
__device__ float g_ncat[V_N * 2 * D_F];
__device__ float g_nh1[V_N * H_F];
__device__ float g_nh2[V_N * H_F];
__device__ float g_ucat[G_N * 3 * D_F];
__device__ float g_ah1[G_N * H_F];
__device__ float g_ah2[G_N * H_F];

// pre-split weights (bf16 hi/lo), layout [N][K] row-major
#define WT_TOTAL 393216
__device__ __nv_bfloat16 g_wthi[WT_TOTAL];
__device__ __nv_bfloat16 g_wtlo[WT_TOTAL];
// offsets (elements)
#define OFF_PE  0
#define OFF_PN  16384
#define OFF_WVA 32768
#define OFF_WVB 65536
#define OFF_WE1 98304
#define OFF_EW1 131072
#define OFF_EW2 196608
#define OFF_NW0 229376
#define OFF_NW1 294912
#define OFF_NW2 360448

typedef unsigned long long ull;

// ---------------- helpers ----------------
__device__ __forceinline__ float softplusf(float x) {
    return fmaxf(x, 0.f) + __logf(1.f + __expf(-fabsf(x)));
}

__device__ __forceinline__ uint32_t smem_to_u32(const void* p) {
    uint32_t a;
    asm("{ .reg .u64 t; cvta.to.shared.u64 t, %1; cvt.u32.u64 %0, t; }" : "=r"(a) : "l"(p));
    return a;
}

__device__ __forceinline__ void mma16816(float* d, const uint32_t* a, const uint32_t* b) {
    asm volatile(
        "mma.sync.aligned.m16n8k16.row.col.f32.bf16.bf16.f32 "
        "{%0,%1,%2,%3}, {%4,%5,%6,%7}, {%8,%9}, {%0,%1,%2,%3};"
        : "+f"(d[0]), "+f"(d[1]), "+f"(d[2]), "+f"(d[3])
        : "r"(a[0]), "r"(a[1]), "r"(a[2]), "r"(a[3]), "r"(b[0]), "r"(b[1]));
}

#define LDM_X4(r, addr) \
    asm volatile("ldmatrix.sync.aligned.m8n8.x4.shared.b16 {%0,%1,%2,%3}, [%4];" \
        : "=r"((r)[0]), "=r"((r)[1]), "=r"((r)[2]), "=r"((r)[3]) : "r"(addr))

#define CP_ASYNC16(dst_u32, src_ptr) \
    asm volatile("cp.async.cg.shared.global [%0], [%1], 16;" :: "r"(dst_u32), "l"(src_ptr))
#define CP_COMMIT() asm volatile("cp.async.commit_group;" ::: "memory")

// ---------------- batched weight prep: fp32 [K][N] -> bf16 hi/lo [N][K] ----------------
__global__ void prep_all(const float* __restrict__ peW, const float* __restrict__ pnW,
                         const float* __restrict__ eW0, const float* __restrict__ eW1,
                         const float* __restrict__ eW2, const float* __restrict__ nW0,
                         const float* __restrict__ nW1, const float* __restrict__ nW2)
{
    int idx = blockIdx.x * blockDim.x + threadIdx.x;
    if (idx >= WT_TOTAL) return;
    const float* W; int K, N, off, rem;
    if      (idx < 32768)  { if (idx < 16384) { W = peW; off = OFF_PE; rem = idx; }
                             else             { W = pnW; off = OFF_PN; rem = idx - 16384; }
                             K = 128; N = 128; }
    else if (idx < 131072) { int r = idx - 32768;
                             if      (r < 32768) { W = eW0;             off = OFF_WVA; rem = r; }
                             else if (r < 65536) { W = eW0 + 128 * 256; off = OFF_WVB; rem = r - 32768; }
                             else                { W = eW0 + 256 * 256; off = OFF_WE1; rem = r - 65536; }
                             K = 128; N = 256; }
    else if (idx < 196608) { W = eW1; off = OFF_EW1; rem = idx - 131072; K = 256; N = 256; }
    else if (idx < 229376) { W = eW2; off = OFF_EW2; rem = idx - 196608; K = 256; N = 128; }
    else if (idx < 294912) { W = nW0; off = OFF_NW0; rem = idx - 229376; K = 256; N = 256; }
    else if (idx < 360448) { W = nW1; off = OFF_NW1; rem = idx - 294912; K = 256; N = 256; }
    else                   { W = nW2; off = OFF_NW2; rem = idx - 360448; K = 256; N = 128; }
    int k = rem / N, n = rem % N;
    float x = W[rem];
    __nv_bfloat16 h = __float2bfloat16_rn(x);
    __nv_bfloat16 l = __float2bfloat16_rn(x - __bfloat162float(h));
    size_t pos = (size_t)off + (size_t)n * K + k;
    g_wthi[pos] = h;
    g_wtlo[pos] = l;
}

// ---------------- mma.sync GEMM ----------------
// out = act(A@W^T + bias + E0[i0] + E1[i1] + E2[i2]) (+atomic scatter, +skip)
// Block tile 128x128, BK=32 bf16, 256 thr = 8 warps (4m x 2n), warp tile 32x64.
// 3-way bf16 split (AhBh + AhBl + AlBh), fp32 accumulate. ldmatrix fragments.
#define AS 40        // smem row stride in halves (80B -> ldmatrix conflict-free)
#define BUF_H 5120   // halves per buffer (128 * 40)
#define STG_H 20480  // halves per stage (Ah, Al, Bh, Bl)

__global__ __launch_bounds__(256, 2)
void mma_gemm(const float* __restrict__ A, int K, int Ntot,
              const __nv_bfloat16* __restrict__ Whi, const __nv_bfloat16* __restrict__ Wlo,
              const float* __restrict__ bias,
              const float* __restrict__ E0, const int* __restrict__ E0i,
              const float* __restrict__ E1, const int* __restrict__ E1i,
              const float* __restrict__ E2, const int* __restrict__ E2i,
              const float* __restrict__ skip,
              float* __restrict__ at0, const int* __restrict__ at0i,
              float* __restrict__ at1, const int* __restrict__ at1i,
              float* __restrict__ out, int M, int act)
{
    extern __shared__ __align__(16) __nv_bfloat16 sm[];
    const uint32_t sbase = smem_to_u32(sm);
    const int tid  = threadIdx.x;
    const int lane = tid & 31, wid = tid >> 5;
    const int wm = wid & 3, wn = wid >> 2;
    const int colblk = blockIdx.x << 7;
    const int row0   = blockIdx.y << 7;

    const int nch = K >> 5;

    // A loader mapping: row = tid>>1 (0..127), half = tid&1 (16 floats each)
    const int lar = tid >> 1, lah = tid & 1;
    const bool larv = (row0 + lar) < M;
    const float* aRow = A + (size_t)(row0 + lar) * K + lah * 16;

    // ldmatrix lane->address offsets (in halves)
    const int t8 = lane >> 3, j8 = lane & 7;
    const int aoff = (wm * 32 + (t8 & 1) * 8 + j8) * AS + (t8 >> 1) * 8;
    const int boff = (wn * 64 + (t8 >> 1) * 8 + j8) * AS + (t8 & 1) * 8;

    float acc[2][8][4];
#pragma unroll
    for (int mt = 0; mt < 2; mt++)
#pragma unroll
        for (int nt = 0; nt < 8; nt++)
#pragma unroll
            for (int c = 0; c < 4; c++) acc[mt][nt][c] = 0.f;

    float4 ar[4];

#define LDG_A(c) do { \
    if (larv) { \
        const float4* _p = (const float4*)(aRow + (c) * 32); \
        ar[0] = _p[0]; ar[1] = _p[1]; ar[2] = _p[2]; ar[3] = _p[3]; \
    } else { \
        ar[0] = ar[1] = ar[2] = ar[3] = make_float4(0.f, 0.f, 0.f, 0.f); \
    } } while (0)

#define STS_A(st) do { \
    const int _base = (st) * STG_H + lar * AS + lah * 16; \
    _Pragma("unroll") \
    for (int q = 0; q < 4; q++) { \
        __nv_bfloat162 h0 = __floats2bfloat162_rn(ar[q].x, ar[q].y); \
        __nv_bfloat162 h1 = __floats2bfloat162_rn(ar[q].z, ar[q].w); \
        float2 f0 = __bfloat1622float2(h0); \
        float2 f1 = __bfloat1622float2(h1); \
        __nv_bfloat162 l0 = __floats2bfloat162_rn(ar[q].x - f0.x, ar[q].y - f0.y); \
        __nv_bfloat162 l1 = __floats2bfloat162_rn(ar[q].z - f1.x, ar[q].w - f1.y); \
        ull hp = (ull)(*(uint32_t*)&h0) | ((ull)(*(uint32_t*)&h1) << 32); \
        ull lp = (ull)(*(uint32_t*)&l0) | ((ull)(*(uint32_t*)&l1) << 32); \
        *(ull*)&sm[_base + q * 4]         = hp; \
        *(ull*)&sm[_base + BUF_H + q * 4] = lp; \
    } } while (0)

#define CPA_B(c, st) do { \
    const int _boff = (st) * STG_H + 2 * BUF_H; \
    _Pragma("unroll") \
    for (int i = 0; i < 2; i++) { \
        int _idx = tid + i * 256; \
        int _r = _idx >> 2, _s = _idx & 3; \
        const __nv_bfloat16* _sh = Whi + (size_t)(colblk + _r) * K + (c) * 32 + _s * 8; \
        const __nv_bfloat16* _sl = Wlo + (size_t)(colblk + _r) * K + (c) * 32 + _s * 8; \
        uint32_t _dh = sbase + (uint32_t)(_boff + _r * AS + _s * 8) * 2; \
        uint32_t _dl = _dh + BUF_H * 2; \
        CP_ASYNC16(_dh, _sh); \
        CP_ASYNC16(_dl, _sl); \
    } } while (0)

    // prologue
    LDG_A(0);
    CPA_B(0, 0);
    CP_COMMIT();
    STS_A(0);

    for (int c = 0; c < nch; c++) {
        const int nxt = c + 1;
        if (nxt < nch) {
            LDG_A(nxt);
            CPA_B(nxt, nxt & 1);
            CP_COMMIT();
            asm volatile("cp.async.wait_group 1;" ::: "memory");
        } else {
            asm volatile("cp.async.wait_group 0;" ::: "memory");
        }
        __syncthreads();

        // compute stage c&1
        {
            const int S = (c & 1) * STG_H;
            const uint32_t aAddrH = sbase + (uint32_t)(S + aoff) * 2;
            const uint32_t bAddrH = sbase + (uint32_t)(S + 2 * BUF_H + boff) * 2;
#pragma unroll
            for (int ks = 0; ks < 2; ks++) {
                uint32_t ah[2][4], al[2][4];
#pragma unroll
                for (int mt = 0; mt < 2; mt++) {
                    uint32_t a0 = aAddrH + (uint32_t)(mt * 16 * AS + ks * 16) * 2;
                    LDM_X4(ah[mt], a0);
                    LDM_X4(al[mt], a0 + BUF_H * 2);
                }
#pragma unroll
                for (int g = 0; g < 4; g++) {
                    uint32_t bh[4], bl[4];
                    uint32_t b0 = bAddrH + (uint32_t)(g * 16 * AS + ks * 16) * 2;
                    LDM_X4(bh, b0);
                    LDM_X4(bl, b0 + BUF_H * 2);
#pragma unroll
                    for (int mt = 0; mt < 2; mt++) {
                        mma16816(acc[mt][2 * g + 0], ah[mt], bh + 0);
                        mma16816(acc[mt][2 * g + 0], ah[mt], bl + 0);
                        mma16816(acc[mt][2 * g + 0], al[mt], bh + 0);
                        mma16816(acc[mt][2 * g + 1], ah[mt], bh + 2);
                        mma16816(acc[mt][2 * g + 1], ah[mt], bl + 2);
                        mma16816(acc[mt][2 * g + 1], al[mt], bh + 2);
                    }
                }
            }
        }
        if (nxt < nch) STS_A(nxt & 1);
        __syncthreads();
    }

    // ---- epilogue ----
#pragma unroll
    for (int mt = 0; mt < 2; mt++) {
#pragma unroll
        for (int h = 0; h < 2; h++) {
            const int grow = row0 + wm * 32 + mt * 16 + (lane >> 2) + h * 8;
            if (grow >= M) continue;
            const float* p0 = E0 ? E0 + (size_t)E0i[grow] * Ntot : (const float*)0;
            const float* p1 = E1 ? E1 + (size_t)E1i[grow] * Ntot : (const float*)0;
            const float* p2 = E2 ? E2 + (size_t)E2i[grow] * Ntot : (const float*)0;
            float* q0 = at0 ? at0 + (size_t)at0i[grow] * Ntot : (float*)0;
            float* q1 = at1 ? at1 + (size_t)at1i[grow] * Ntot : (float*)0;
            const float* sk = skip ? skip + (size_t)grow * Ntot : (const float*)0;
            float* op = out + (size_t)grow * Ntot;
#pragma unroll
            for (int nt = 0; nt < 8; nt++) {
                const int col = colblk + wn * 64 + nt * 8 + (lane & 3) * 2;
                float v0 = acc[mt][nt][h * 2 + 0];
                float v1 = acc[mt][nt][h * 2 + 1];
                if (bias) { v0 += bias[col]; v1 += bias[col + 1]; }
                if (p0)   { v0 += p0[col];  v1 += p0[col + 1]; }
                if (p1)   { v0 += p1[col];  v1 += p1[col + 1]; }
                if (p2)   { v0 += p2[col];  v1 += p2[col + 1]; }
                if (act)  { v0 = softplusf(v0); v1 = softplusf(v1); }
                if (q0)   { atomicAdd(q0 + col, v0); atomicAdd(q0 + col + 1, v1); }
                if (q1)   { atomicAdd(q1 + col, v0); atomicAdd(q1 + col + 1, v1); }
                if (sk)   { v0 += sk[col]; v1 += sk[col + 1]; }
                float2 o; o.x = v0; o.y = v1;
                *(float2*)(op + col) = o;
            }
        }
    }
}

// ---------------- small GEMM (graph-level, 32 rows) ----------------
__global__ void small_gemm(const float* __restrict__ A, int lda,
                           const float* __restrict__ B, int ldb,
                           const float* __restrict__ bias,
                           const float* __restrict__ skip,
                           float* __restrict__ out,
                           int M, int N, int K, int act)
{
    int idx = blockIdx.x * blockDim.x + threadIdx.x;
    if (idx >= M * N) return;
    int row = idx / N, col = idx % N;
    float s = bias ? bias[col] : 0.f;
    const float* a = A + (size_t)row * lda;
    for (int k = 0; k < K; k++) s += a[k] * B[(size_t)k * ldb + col];
    if (act)  s = softplusf(s);
    if (skip) s += skip[(size_t)row * N + col];
    out[(size_t)row * N + col] = s;
}

// ---------------- misc kernels ----------------
__global__ void zero_kernel() {
    int i = blockIdx.x * blockDim.x + threadIdx.x;
    if (i < V_N * D_F) g_ve_sum[i] = 0.f;
    if (i < G_N * D_F) { g_ue_sum[i] = 0.f; g_uv_sum[i] = 0.f; }
    if (i < V_N) g_ve_cnt[i] = 0;
    if (i < G_N) { g_ue_cnt[i] = 0; g_uv_cnt[i] = 0; }
}

__global__ void count_edges(const int* __restrict__ src, const int* __restrict__ dst,
                            const int* __restrict__ n2g) {
    int i = blockIdx.x * blockDim.x + threadIdx.x;
    if (i >= E_N) return;
    int g = n2g[src[i]];
    g_gsrc[i] = g;
    atomicAdd(&g_ve_cnt[dst[i]], 1);
    atomicAdd(&g_ue_cnt[g], 1);
}

__global__ void count_nodes(const int* __restrict__ n2g) {
    int i = blockIdx.x * blockDim.x + threadIdx.x;
    if (i >= V_N) return;
    atomicAdd(&g_uv_cnt[n2g[i]], 1);
}

__global__ void build_ncat() {
    int i = blockIdx.x * blockDim.x + threadIdx.x;
    if (i >= V_N * 2 * D_F) return;
    int row = i >> 8, c = i & 255;
    float v;
    if (c < D_F) v = g_v_pre[row * D_F + c];
    else         v = g_ve_sum[row * D_F + (c - D_F)] / fmaxf((float)g_ve_cnt[row], 1.f);
    g_ncat[i] = v;
}

__global__ void build_ucat() {
    int i = blockIdx.x * blockDim.x + threadIdx.x;
    if (i >= G_N * 3 * D_F) return;
    int row = i / (3 * D_F), c = i % (3 * D_F);
    float v;
    if (c < D_F)          v = g_u_pre[row * D_F + c];
    else if (c < 2 * D_F) v = g_ue_sum[row * D_F + (c - D_F)]     / fmaxf((float)g_ue_cnt[row], 1.f);
    else                  v = g_uv_sum[row * D_F + (c - 2 * D_F)] / fmaxf((float)g_uv_cnt[row], 1.f);
    g_ucat[i] = v;
}

// ---------------- launch ----------------
extern "C" void kernel_launch(void* const* d_in, const int* in_sizes, int n_in,
                              void* d_out, int out_size) {
    (void)in_sizes; (void)n_in; (void)out_size;
    const float* edge_feat  = (const float*)d_in[0];
    const float* node_feat  = (const float*)d_in[1];
    const float* graph_attr = (const float*)d_in[2];
    const int*   src = (const int*)d_in[3];
    const int*   dst = (const int*)d_in[4];
    const int*   n2g = (const int*)d_in[5];
    const float* peW = (const float*)d_in[6],  *peb = (const float*)d_in[7];
    const float* pnW = (const float*)d_in[8],  *pnb = (const float*)d_in[9];
    const float* paW = (const float*)d_in[10], *pab = (const float*)d_in[11];
    const float* eW0 = (const float*)d_in[12], *eb0 = (const float*)d_in[13];
    const float* eW1 = (const float*)d_in[14], *eb1 = (const float*)d_in[15];
    const float* eW2 = (const float*)d_in[16], *eb2 = (const float*)d_in[17];
    const float* nW0 = (const float*)d_in[18], *nb0 = (const float*)d_in[19];
    const float* nW1 = (const float*)d_in[20], *nb1 = (const float*)d_in[21];
    const float* nW2 = (const float*)d_in[22], *nb2 = (const float*)d_in[23];
    const float* aW0 = (const float*)d_in[24], *ab0 = (const float*)d_in[25];
    const float* aW1 = (const float*)d_in[26], *ab1 = (const float*)d_in[27];
    const float* aW2 = (const float*)d_in[28], *ab2 = (const float*)d_in[29];

    float* out_e = (float*)d_out;
    float* out_v = out_e + (size_t)E_N * D_F;
    float* out_u = out_v + (size_t)V_N * D_F;

    float *e_pre, *v_pre, *u_pre, *Va, *Vb, *U0, *UN0, *eh1, *eh2;
    float *ve_sum, *ue_sum, *uv_sum, *ncat, *nh1, *nh2, *ucat, *ah1, *ah2;
    int *gsrc;
    __nv_bfloat16 *wthi, *wtlo;
#define SYMX(p, s, T) { void* _t; cudaGetSymbolAddress(&_t, s); p = (T*)_t; }
    SYMX(e_pre, g_e_pre, float)   SYMX(v_pre, g_v_pre, float)   SYMX(u_pre, g_u_pre, float)
    SYMX(Va, g_Va, float)         SYMX(Vb, g_Vb, float)
    SYMX(U0, g_U0, float)         SYMX(UN0, g_UN0, float)
    SYMX(eh1, g_eh1, float)       SYMX(eh2, g_eh2, float)
    SYMX(ve_sum, g_ve_sum, float) SYMX(ue_sum, g_ue_sum, float) SYMX(uv_sum, g_uv_sum, float)
    SYMX(ncat, g_ncat, float)     SYMX(nh1, g_nh1, float)       SYMX(nh2, g_nh2, float)
    SYMX(ucat, g_ucat, float)     SYMX(ah1, g_ah1, float)       SYMX(ah2, g_ah2, float)
    SYMX(gsrc, g_gsrc, int)
    SYMX(wthi, g_wthi, __nv_bfloat16)  SYMX(wtlo, g_wtlo, __nv_bfloat16)
#undef SYMX

    const int SMEM = 2 * STG_H * 2;  // 81920 bytes
    cudaFuncSetAttribute(mma_gemm, cudaFuncAttributeMaxDynamicSharedMemorySize, SMEM);

    const int TE = (E_N + 127) / 128;   // 2344
    const int TV = (V_N + 127) / 128;   // 157
    const float* Z = 0; const int* ZI = 0; float* ZF = 0;

    zero_kernel<<<(V_N * D_F + 255) / 256, 256>>>();
    count_edges<<<(E_N + 255) / 256, 256>>>(src, dst, n2g);
    count_nodes<<<(V_N + 255) / 256, 256>>>(n2g);
    prep_all<<<(WT_TOTAL + 255) / 256, 256>>>(peW, pnW, eW0, eW1, eW2, nW0, nW1, nW2);

#define GEMM(NT, NB, ...) mma_gemm<<<dim3((NT)/128, (NB)), 256, SMEM>>>(__VA_ARGS__)

    // pre-dense
    GEMM(128, TE, edge_feat, 128, 128, wthi + OFF_PE, wtlo + OFF_PE, peb,
         Z, ZI, Z, ZI, Z, ZI, Z, ZF, ZI, ZF, ZI, e_pre, E_N, 1);
    GEMM(128, TV, node_feat, 128, 128, wthi + OFF_PN, wtlo + OFF_PN, pnb,
         Z, ZI, Z, ZI, Z, ZI, Z, ZF, ZI, ZF, ZI, v_pre, V_N, 1);
    small_gemm<<<(G_N * D_F + 255) / 256, 256>>>(graph_attr, D_F, paW, D_F, pab, 0,
                                                 u_pre, G_N, D_F, D_F, 1);

    // factored first edge layer partials
    GEMM(256, TV, v_pre, 128, 256, wthi + OFF_WVA, wtlo + OFF_WVA, Z,
         Z, ZI, Z, ZI, Z, ZI, Z, ZF, ZI, ZF, ZI, Va, V_N, 0);
    GEMM(256, TV, v_pre, 128, 256, wthi + OFF_WVB, wtlo + OFF_WVB, Z,
         Z, ZI, Z, ZI, Z, ZI, Z, ZF, ZI, ZF, ZI, Vb, V_N, 0);
    small_gemm<<<(G_N * H_F + 255) / 256, 256>>>(u_pre, D_F, eW0 + 384 * H_F, H_F, 0, 0,
                                                 U0, G_N, H_F, D_F, 0);
    small_gemm<<<(G_N * H_F + 255) / 256, 256>>>(u_pre, D_F, nW0 + 256 * H_F, H_F, 0, 0,
                                                 UN0, G_N, H_F, D_F, 0);

    // edge MLP
    GEMM(256, TE, e_pre, 128, 256, wthi + OFF_WE1, wtlo + OFF_WE1, eb0,
         Va, src, Vb, dst, U0, gsrc, Z, ZF, ZI, ZF, ZI, eh1, E_N, 1);
    GEMM(256, TE, eh1, 256, 256, wthi + OFF_EW1, wtlo + OFF_EW1, eb1,
         Z, ZI, Z, ZI, Z, ZI, Z, ZF, ZI, ZF, ZI, eh2, E_N, 1);
    GEMM(128, TE, eh2, 256, 128, wthi + OFF_EW2, wtlo + OFF_EW2, eb2,
         Z, ZI, Z, ZI, Z, ZI, edge_feat,
         ve_sum, dst, ue_sum, gsrc, out_e, E_N, 1);

    // node MLP
    build_ncat<<<(V_N * 2 * D_F + 255) / 256, 256>>>();
    GEMM(256, TV, ncat, 256, 256, wthi + OFF_NW0, wtlo + OFF_NW0, nb0,
         UN0, n2g, Z, ZI, Z, ZI, Z, ZF, ZI, ZF, ZI, nh1, V_N, 1);
    GEMM(256, TV, nh1, 256, 256, wthi + OFF_NW1, wtlo + OFF_NW1, nb1,
         Z, ZI, Z, ZI, Z, ZI, Z, ZF, ZI, ZF, ZI, nh2, V_N, 1);
    GEMM(128, TV, nh2, 256, 128, wthi + OFF_NW2, wtlo + OFF_NW2, nb2,
         Z, ZI, Z, ZI, Z, ZI, node_feat,
         uv_sum, n2g, ZF, ZI, out_v, V_N, 1);

    // graph-attr MLP
    build_ucat<<<(G_N * 3 * D_F + 255) / 256, 256>>>();
    small_gemm<<<(G_N * H_F + 255) / 256, 256>>>(ucat, 3 * D_F, aW0, H_F, ab0, 0,
                                                 ah1, G_N, H_F, 3 * D_F, 1);
    small_gemm<<<(G_N * H_F + 255) / 256, 256>>>(ah1, H_F, aW1, H_F, ab1, 0,
                                                 ah2, G_N, H_F, H_F, 1);
    small_gemm<<<(G_N * D_F + 255) / 256, 256>>>(ah2, H_F, aW2, D_F, ab2, graph_attr,
                                                 out_u, G_N, D_F, H_F, 1);
}